// round 1
// baseline (speedup 1.0000x reference)
#include <cuda_runtime.h>

// Problem constants
#define BDIM 2
#define TDIM 4096
#define CDIM 768
#define HDIM 12
#define DDIM 64
#define N3DIM 2304   // 3*C

// Scratch (device globals: no allocation allowed in kernel_launch)
__device__ float g_qT[BDIM*HDIM*DDIM*TDIM];   // [b,h,d,t], pre-scaled by 0.125
__device__ float g_kT[BDIM*HDIM*DDIM*TDIM];   // [b,h,d,t]
__device__ float g_v [BDIM*HDIM*TDIM*DDIM];   // [b,h,t,d]
__device__ float g_y [BDIM*TDIM*CDIM];        // [b,t,c] attention output

// ---------------------------------------------------------------------------
// Kernel 1: QKV GEMM.  x[8192,768] @ W[768,2304] + b -> scattered into
// g_qT / g_kT (transposed per-head) and g_v.  64x64 block tile, 256 threads,
// 4x4 per-thread micro-tile, K-step 16.
// Each 64-wide N tile maps to exactly one (which,head): 2304 = 3*12*64.
// ---------------------------------------------------------------------------
__global__ __launch_bounds__(256) void qkv_gemm(const float* __restrict__ x,
                                                const float* __restrict__ W,
                                                const float* __restrict__ bias) {
    __shared__ float As[16][68];   // [k][m] transposed
    __shared__ float Bs[16][68];   // [k][n]
    const int tid = threadIdx.x;
    const int tx = tid & 15, ty = tid >> 4;
    const int bm = blockIdx.y * 64;
    const int bn = blockIdx.x * 64;
    const int which = bn / CDIM;           // 0=q, 1=k, 2=v (block-constant)
    const int h     = (bn % CDIM) / DDIM;  // head (block-constant)

    const int arow = tid >> 2;         // 0..63
    const int acg  = (tid & 3) * 4;    // 0,4,8,12
    const int brow = tid >> 4;         // 0..15
    const int bcg  = (tid & 15) * 4;   // 0..60

    float c[4][4] = {};
    for (int k0 = 0; k0 < CDIM; k0 += 16) {
        float4 a4 = *(const float4*)(x + (size_t)(bm + arow) * CDIM + k0 + acg);
        float4 b4 = *(const float4*)(W + (size_t)(k0 + brow) * N3DIM + bn + bcg);
        __syncthreads();
        As[acg+0][arow] = a4.x; As[acg+1][arow] = a4.y;
        As[acg+2][arow] = a4.z; As[acg+3][arow] = a4.w;
        *(float4*)&Bs[brow][bcg] = b4;
        __syncthreads();
        #pragma unroll
        for (int kk = 0; kk < 16; kk++) {
            float4 av = *(float4*)&As[kk][4*ty];
            float4 bv = *(float4*)&Bs[kk][4*tx];
            float a[4] = {av.x, av.y, av.z, av.w};
            float b[4] = {bv.x, bv.y, bv.z, bv.w};
            #pragma unroll
            for (int i = 0; i < 4; i++)
                #pragma unroll
                for (int j = 0; j < 4; j++)
                    c[i][j] = fmaf(a[i], b[j], c[i][j]);
        }
    }

    float4 bq = *(const float4*)(bias + bn + 4*tx);
    float bb[4] = {bq.x, bq.y, bq.z, bq.w};
    const int bt0   = bm + 4*ty;           // first global row of this thread
    const int batch = bt0 >> 12;           // / 4096
    const int t0    = bt0 & (TDIM - 1);
    const int dg    = 4*tx;

    if (which == 2) {
        // V: [b,h,t,d]  (float4 along d)
        #pragma unroll
        for (int i = 0; i < 4; i++) {
            float4 o = make_float4(c[i][0]+bb[0], c[i][1]+bb[1],
                                   c[i][2]+bb[2], c[i][3]+bb[3]);
            *(float4*)(g_v + ((size_t)(batch*HDIM + h)*TDIM + t0 + i)*DDIM + dg) = o;
        }
    } else {
        // Q/K transposed: [b,h,d,t]  (float4 along t = the 4 row results)
        float* dst = (which == 0) ? g_qT : g_kT;
        const float sc = (which == 0) ? 0.125f : 1.0f;   // fold 1/sqrt(64) into Q
        #pragma unroll
        for (int j = 0; j < 4; j++) {
            float4 o = make_float4((c[0][j]+bb[j])*sc, (c[1][j]+bb[j])*sc,
                                   (c[2][j]+bb[j])*sc, (c[3][j]+bb[j])*sc);
            *(float4*)(dst + ((size_t)(batch*HDIM + h)*DDIM + dg + j)*TDIM + t0) = o;
        }
    }
}

// ---------------------------------------------------------------------------
// Kernel 2: causal flash attention, fp32, online softmax.
// Grid (64 q-tiles, 24 b*h).  Block = 256 threads, 4x4 micro-tile.
// Q tile 64x64 resident; stream K/V tiles 0..qt (causal skip); only the
// diagonal tile is masked.  Heavy blocks scheduled first.
// ---------------------------------------------------------------------------
#define SMEM_FLASH ((3*64*68 + 64*65) * 4)

__global__ __launch_bounds__(256) void flash_attn() {
    extern __shared__ float sm[];
    float* Qs = sm;               // [d][t]  64 x 68
    float* Ks = sm + 64*68;       // [d][t]  64 x 68
    float* Vs = sm + 2*64*68;     // [t][d]  64 x 68
    float* Ps = sm + 3*64*68;     // [q][k]  64 x 65

    const int tid = threadIdx.x;
    const int tx = tid & 15, ty = tid >> 4;
    const int qt = (int)(gridDim.x - 1) - (int)blockIdx.x;  // heavy tiles first
    const int bh = blockIdx.y;
    const int qbase = qt * 64;

    const float* qp = g_qT + (size_t)bh * DDIM * TDIM;
    const float* kp = g_kT + (size_t)bh * DDIM * TDIM;
    const float* vp = g_v  + (size_t)bh * TDIM * DDIM;

    const int cg = (tid & 15) * 4;
    const int r0 = tid >> 4;

    #pragma unroll
    for (int rr = 0; rr < 4; rr++) {
        int d = rr*16 + r0;
        *(float4*)(Qs + d*68 + cg) = *(const float4*)(qp + (size_t)d*TDIM + qbase + cg);
    }

    float m_i[4] = {-1e30f, -1e30f, -1e30f, -1e30f};
    float l_i[4] = {0.f, 0.f, 0.f, 0.f};
    float o[4][4] = {};

    for (int jt = 0; jt <= qt; jt++) {
        const int kb = jt * 64;
        __syncthreads();   // previous PV done; safe to overwrite Ks/Vs (also fences Qs load)
        #pragma unroll
        for (int rr = 0; rr < 4; rr++) {
            int r = rr*16 + r0;
            *(float4*)(Ks + r*68 + cg) = *(const float4*)(kp + (size_t)r*TDIM + kb + cg);
            *(float4*)(Vs + r*68 + cg) = *(const float4*)(vp + (size_t)(kb + r)*DDIM + cg);
        }
        __syncthreads();

        // S = Q . K^T  (scale pre-folded into Q)
        float s[4][4] = {};
        #pragma unroll 8
        for (int d = 0; d < 64; d++) {
            float4 q4 = *(float4*)(Qs + d*68 + 4*ty);
            float4 k4 = *(float4*)(Ks + d*68 + 4*tx);
            float a[4] = {q4.x, q4.y, q4.z, q4.w};
            float b[4] = {k4.x, k4.y, k4.z, k4.w};
            #pragma unroll
            for (int i = 0; i < 4; i++)
                #pragma unroll
                for (int j = 0; j < 4; j++)
                    s[i][j] = fmaf(a[i], b[j], s[i][j]);
        }

        if (jt == qt) {   // only diagonal tile needs the causal mask
            #pragma unroll
            for (int i = 0; i < 4; i++)
                #pragma unroll
                for (int j = 0; j < 4; j++)
                    if (kb + 4*tx + j > qbase + 4*ty + i) s[i][j] = -1e30f;
        }

        // Online softmax update (row reductions across the 16 tx lanes)
        #pragma unroll
        for (int i = 0; i < 4; i++) {
            float mt = fmaxf(fmaxf(s[i][0], s[i][1]), fmaxf(s[i][2], s[i][3]));
            #pragma unroll
            for (int off = 1; off < 16; off <<= 1)
                mt = fmaxf(mt, __shfl_xor_sync(0xffffffffu, mt, off));
            float mn = fmaxf(m_i[i], mt);
            float corr = __expf(m_i[i] - mn);
            m_i[i] = mn;
            float rs = 0.f;
            #pragma unroll
            for (int j = 0; j < 4; j++) { s[i][j] = __expf(s[i][j] - mn); rs += s[i][j]; }
            #pragma unroll
            for (int off = 1; off < 16; off <<= 1)
                rs += __shfl_xor_sync(0xffffffffu, rs, off);
            l_i[i] = l_i[i]*corr + rs;
            #pragma unroll
            for (int j = 0; j < 4; j++) {
                o[i][j] *= corr;
                Ps[(4*ty + i)*65 + 4*tx + j] = s[i][j];
            }
        }
        __syncthreads();

        // O += P . V
        #pragma unroll 8
        for (int k = 0; k < 64; k++) {
            float4 v4 = *(float4*)(Vs + k*68 + 4*tx);
            #pragma unroll
            for (int i = 0; i < 4; i++) {
                float p = Ps[(4*ty + i)*65 + k];
                o[i][0] = fmaf(p, v4.x, o[i][0]);
                o[i][1] = fmaf(p, v4.y, o[i][1]);
                o[i][2] = fmaf(p, v4.z, o[i][2]);
                o[i][3] = fmaf(p, v4.w, o[i][3]);
            }
        }
    }

    const int batch = bh / HDIM, hh = bh % HDIM;
    #pragma unroll
    for (int i = 0; i < 4; i++) {
        float inv = 1.0f / l_i[i];
        float4 o4 = make_float4(o[i][0]*inv, o[i][1]*inv, o[i][2]*inv, o[i][3]*inv);
        *(float4*)(g_y + (size_t)(batch*TDIM + qbase + 4*ty + i)*CDIM + hh*DDIM + 4*tx) = o4;
    }
}

// ---------------------------------------------------------------------------
// Kernel 3: output projection.  g_y[8192,768] @ W_proj[768,768] + b -> d_out
// ---------------------------------------------------------------------------
__global__ __launch_bounds__(256) void proj_gemm(const float* __restrict__ W,
                                                 const float* __restrict__ bias,
                                                 float* __restrict__ out) {
    __shared__ float As[16][68];
    __shared__ float Bs[16][68];
    const int tid = threadIdx.x;
    const int tx = tid & 15, ty = tid >> 4;
    const int bm = blockIdx.y * 64;
    const int bn = blockIdx.x * 64;

    const int arow = tid >> 2;
    const int acg  = (tid & 3) * 4;
    const int brow = tid >> 4;
    const int bcg  = (tid & 15) * 4;

    float c[4][4] = {};
    for (int k0 = 0; k0 < CDIM; k0 += 16) {
        float4 a4 = *(const float4*)(g_y + (size_t)(bm + arow) * CDIM + k0 + acg);
        float4 b4 = *(const float4*)(W + (size_t)(k0 + brow) * CDIM + bn + bcg);
        __syncthreads();
        As[acg+0][arow] = a4.x; As[acg+1][arow] = a4.y;
        As[acg+2][arow] = a4.z; As[acg+3][arow] = a4.w;
        *(float4*)&Bs[brow][bcg] = b4;
        __syncthreads();
        #pragma unroll
        for (int kk = 0; kk < 16; kk++) {
            float4 av = *(float4*)&As[kk][4*ty];
            float4 bv = *(float4*)&Bs[kk][4*tx];
            float a[4] = {av.x, av.y, av.z, av.w};
            float b[4] = {bv.x, bv.y, bv.z, bv.w};
            #pragma unroll
            for (int i = 0; i < 4; i++)
                #pragma unroll
                for (int j = 0; j < 4; j++)
                    c[i][j] = fmaf(a[i], b[j], c[i][j]);
        }
    }

    float4 bq = *(const float4*)(bias + bn + 4*tx);
    float bb[4] = {bq.x, bq.y, bq.z, bq.w};
    #pragma unroll
    for (int i = 0; i < 4; i++) {
        float4 o = make_float4(c[i][0]+bb[0], c[i][1]+bb[1],
                               c[i][2]+bb[2], c[i][3]+bb[3]);
        *(float4*)(out + (size_t)(bm + 4*ty + i)*CDIM + bn + 4*tx) = o;
    }
}

// ---------------------------------------------------------------------------
extern "C" void kernel_launch(void* const* d_in, const int* in_sizes, int n_in,
                              void* d_out, int out_size) {
    // Map inputs by element count (all distinct): robust to ordering.
    const float *x = nullptr, *Wa = nullptr, *ba = nullptr, *Wp = nullptr, *bp = nullptr;
    for (int i = 0; i < n_in; i++) {
        switch (in_sizes[i]) {
            case 6291456: x  = (const float*)d_in[i]; break;   // [2,4096,768]
            case 1769472: Wa = (const float*)d_in[i]; break;   // [768,2304]
            case 2304:    ba = (const float*)d_in[i]; break;
            case 589824:  Wp = (const float*)d_in[i]; break;   // [768,768]
            case 768:     bp = (const float*)d_in[i]; break;
        }
    }

    cudaFuncSetAttribute(flash_attn, cudaFuncAttributeMaxDynamicSharedMemorySize,
                         SMEM_FLASH);

    qkv_gemm<<<dim3(N3DIM/64, (BDIM*TDIM)/64), 256>>>(x, Wa, ba);     // (36,128)
    flash_attn<<<dim3(TDIM/64, BDIM*HDIM), 256, SMEM_FLASH>>>();      // (64,24)
    proj_gemm<<<dim3(CDIM/64, (BDIM*TDIM)/64), 256>>>(Wp, bp, (float*)d_out); // (12,128)
}

// round 3
// speedup vs baseline: 3.3865x; 3.3865x over previous
#include <cuda_runtime.h>
#include <cuda_bf16.h>
#include <cstdint>

// ---------------------------------------------------------------------------
// Problem constants
// ---------------------------------------------------------------------------
#define BDIM 2
#define TDIM 4096
#define CDIM 768
#define HDIM 12
#define DDIM 64
#define N3DIM 2304            // 3*C
#define MTOT  (BDIM*TDIM)     // 8192

// ---------------------------------------------------------------------------
// Device scratch (bf16 split operands; no allocation in kernel_launch)
// ---------------------------------------------------------------------------
__device__ __align__(16) __nv_bfloat16 g_xhi[MTOT*CDIM],    g_xlo[MTOT*CDIM];
__device__ __align__(16) __nv_bfloat16 g_yhi[MTOT*CDIM],    g_ylo[MTOT*CDIM];
__device__ __align__(16) __nv_bfloat16 g_WaThi[N3DIM*CDIM], g_WaTlo[N3DIM*CDIM]; // [N,K]
__device__ __align__(16) __nv_bfloat16 g_WpThi[CDIM*CDIM],  g_WpTlo[CDIM*CDIM];  // [N,K]
// q/k/v split, [b*h][t][d] row-major, q pre-scaled by 0.125
__device__ __align__(16) __nv_bfloat16 g_qhi[BDIM*HDIM*TDIM*DDIM], g_qlo[BDIM*HDIM*TDIM*DDIM];
__device__ __align__(16) __nv_bfloat16 g_khi[BDIM*HDIM*TDIM*DDIM], g_klo[BDIM*HDIM*TDIM*DDIM];
__device__ __align__(16) __nv_bfloat16 g_vhi[BDIM*HDIM*TDIM*DDIM], g_vlo[BDIM*HDIM*TDIM*DDIM];

// ---------------------------------------------------------------------------
// Helpers (all sm_80-legal: mma.sync bf16, ldmatrix, cp.async)
// ---------------------------------------------------------------------------
__device__ __forceinline__ uint32_t smem_u32(const void* p) {
    uint32_t a;
    asm("{ .reg .u64 t; cvta.to.shared.u64 t, %1; cvt.u32.u64 %0, t; }"
        : "=r"(a) : "l"(p));
    return a;
}
#define SW128(off) ((off) ^ (((off) >> 3) & 0x70))

__device__ __forceinline__ void cp16(uint32_t dst, const void* src) {
    asm volatile("cp.async.cg.shared.global [%0], [%1], 16;"
                 :: "r"(dst), "l"(src) : "memory");
}
#define CP_COMMIT() asm volatile("cp.async.commit_group;" ::: "memory")
#define CP_WAIT0()  asm volatile("cp.async.wait_group 0;"  ::: "memory")

__device__ __forceinline__ void ldm_x4(uint32_t a, uint32_t& r0, uint32_t& r1,
                                       uint32_t& r2, uint32_t& r3) {
    asm volatile("ldmatrix.sync.aligned.m8n8.x4.shared.b16 {%0,%1,%2,%3}, [%4];"
                 : "=r"(r0), "=r"(r1), "=r"(r2), "=r"(r3) : "r"(a));
}
__device__ __forceinline__ void ldm_x4t(uint32_t a, uint32_t& r0, uint32_t& r1,
                                        uint32_t& r2, uint32_t& r3) {
    asm volatile("ldmatrix.sync.aligned.m8n8.x4.trans.shared.b16 {%0,%1,%2,%3}, [%4];"
                 : "=r"(r0), "=r"(r1), "=r"(r2), "=r"(r3) : "r"(a));
}
__device__ __forceinline__ void mma_bf16(float (&c)[4], const uint32_t (&a)[4],
                                         uint32_t b0, uint32_t b1) {
    asm volatile("mma.sync.aligned.m16n8k16.row.col.f32.bf16.bf16.f32 "
                 "{%0,%1,%2,%3}, {%4,%5,%6,%7}, {%8,%9}, {%0,%1,%2,%3};"
                 : "+f"(c[0]), "+f"(c[1]), "+f"(c[2]), "+f"(c[3])
                 : "r"(a[0]), "r"(a[1]), "r"(a[2]), "r"(a[3]), "r"(b0), "r"(b1));
}
// pack {v0 -> low half, v1 -> high half}
__device__ __forceinline__ uint32_t pk2(float v0, float v1) {
    uint32_t r;
    asm("cvt.rn.bf16x2.f32 %0, %1, %2;" : "=r"(r) : "f"(v1), "f"(v0));
    return r;
}
__device__ __forceinline__ float ex2f(float x) {
    float y; asm("ex2.approx.ftz.f32 %0, %1;" : "=f"(y) : "f"(x)); return y;
}
// split-pack (v0,v1) into bf16 hi pair + residual lo pair, store both
__device__ __forceinline__ void split_store(float v0, float v1,
                                            __nv_bfloat16* hi, __nv_bfloat16* lo,
                                            size_t idx) {
    uint32_t h = pk2(v0, v1);
    float r0 = v0 - __uint_as_float(h << 16);
    float r1 = v1 - __uint_as_float(h & 0xffff0000u);
    *(uint32_t*)(hi + idx) = h;
    *(uint32_t*)(lo + idx) = pk2(r0, r1);
}

// ---------------------------------------------------------------------------
// Conversion kernels
// ---------------------------------------------------------------------------
__global__ __launch_bounds__(256) void split_bf16(const float* __restrict__ in,
                                                  __nv_bfloat16* __restrict__ hi,
                                                  __nv_bfloat16* __restrict__ lo,
                                                  int n2) {
    int i = blockIdx.x * blockDim.x + threadIdx.x;
    if (i >= n2) return;
    float2 v = ((const float2*)in)[i];
    uint32_t h = pk2(v.x, v.y);
    float r0 = v.x - __uint_as_float(h << 16);
    float r1 = v.y - __uint_as_float(h & 0xffff0000u);
    ((uint32_t*)hi)[i] = h;
    ((uint32_t*)lo)[i] = pk2(r0, r1);
}

// W [K,N] fp32 -> hiT/loT [N,K] bf16 (transpose + split). block (32,8).
__global__ __launch_bounds__(256) void wsplit_T(const float* __restrict__ W,
                                                __nv_bfloat16* __restrict__ hiT,
                                                __nv_bfloat16* __restrict__ loT,
                                                int K, int N) {
    __shared__ float tile[32][33];
    const int tx = threadIdx.x, ty = threadIdx.y;
    const int bn = blockIdx.x * 32, bk = blockIdx.y * 32;
    #pragma unroll
    for (int i = 0; i < 4; i++)
        tile[ty + 8*i][tx] = W[(size_t)(bk + ty + 8*i) * N + bn + tx];
    __syncthreads();
    #pragma unroll
    for (int i = 0; i < 4; i++) {
        float v = tile[tx][ty + 8*i];
        __nv_bfloat16 h = __float2bfloat16(v);
        float l = v - __bfloat162float(h);
        size_t o = (size_t)(bn + ty + 8*i) * K + bk + tx;
        hiT[o] = h;
        loT[o] = __float2bfloat16(l);
    }
}

// ---------------------------------------------------------------------------
// Shared split-bf16 HMMA GEMM mainloop.
// C[128,128] fp32 = Ahi.B^T(hi) + Ahi.B^T(lo) + Alo.B^T(hi) over K=768.
// A: [M,768] bf16 row-major. B: [N,768] bf16 row-major (weightsT).
// 256 thr = 8 warps (2 m x 4 n), warp tile 64x32, K-chunk 64, 2-stage cp.async.
// smem stage (64KB): Ahi@0 Alo@16K Bhi@32K Blo@48K, rows 128B SW128.
// acc[mf][nf][4]: mf rows 16, nf cols 8.
// ---------------------------------------------------------------------------
#define GSMEM (2*65536)

__device__ __forceinline__ void gemm_issue(const __nv_bfloat16* Ahi,
                                           const __nv_bfloat16* Alo,
                                           const __nv_bfloat16* Bhi,
                                           const __nv_bfloat16* Blo,
                                           int am0, int bn0, int k0,
                                           uint32_t stbase, int tid) {
    #pragma unroll
    for (int arr = 0; arr < 4; arr++) {
        const __nv_bfloat16* base = arr == 0 ? Ahi : arr == 1 ? Alo
                                  : arr == 2 ? Bhi : Blo;
        const int r0 = (arr < 2) ? am0 : bn0;
        #pragma unroll
        for (int i = 0; i < 4; i++) {
            int s2 = tid + (i << 8);          // 0..1023
            int row = s2 >> 3, c16 = s2 & 7;
            cp16(stbase + (arr << 14) + SW128((uint32_t)(row*128 + (c16 << 4))),
                 base + (size_t)(r0 + row) * 768 + k0 + (c16 << 3));
        }
    }
    CP_COMMIT();
}

__device__ __forceinline__ void gemm_main(const __nv_bfloat16* Ahi,
                                          const __nv_bfloat16* Alo,
                                          const __nv_bfloat16* Bhi,
                                          const __nv_bfloat16* Blo,
                                          int am0, int bn0,
                                          float (&acc)[4][4][4], char* sm) {
    const int tid = threadIdx.x;
    const int wid = tid >> 5, lane = tid & 31;
    const uint32_t sb = smem_u32(sm);
    const int wm0 = (wid & 1) * 64;
    const int wn0 = (wid >> 1) * 32;
    const int r = lane & 7, g = lane >> 3;

    gemm_issue(Ahi, Alo, Bhi, Blo, am0, bn0, 0, sb, tid);

    for (int c = 0; c < 12; c++) {
        CP_WAIT0();
        __syncthreads();
        if (c < 11)
            gemm_issue(Ahi, Alo, Bhi, Blo, am0, bn0, (c+1)*64,
                       sb + (uint32_t)(((c+1)&1) << 16), tid);
        const uint32_t st = sb + (uint32_t)((c & 1) << 16);
        #pragma unroll
        for (int kf = 0; kf < 4; kf++) {
            const int k0 = kf * 16;
            uint32_t ah[4][4], al[4][4];
            #pragma unroll
            for (int mf = 0; mf < 4; mf++) {
                uint32_t off = SW128((uint32_t)(
                    (wm0 + mf*16 + ((g & 1) ? 8 : 0) + r) * 128 +
                    (k0 + ((g & 2) ? 8 : 0)) * 2));
                ldm_x4(st + off,         ah[mf][0], ah[mf][1], ah[mf][2], ah[mf][3]);
                ldm_x4(st + 16384 + off, al[mf][0], al[mf][1], al[mf][2], al[mf][3]);
            }
            uint32_t bh[4][2], bl[4][2];
            #pragma unroll
            for (int nb = 0; nb < 2; nb++) {
                uint32_t off = SW128((uint32_t)(
                    (wn0 + nb*16 + ((g & 2) ? 8 : 0) + r) * 128 +
                    (k0 + ((g & 1) ? 8 : 0)) * 2));
                uint32_t t0, t1, t2, t3;
                ldm_x4(st + 32768 + off, t0, t1, t2, t3);
                bh[2*nb][0] = t0; bh[2*nb][1] = t1;
                bh[2*nb+1][0] = t2; bh[2*nb+1][1] = t3;
                ldm_x4(st + 49152 + off, t0, t1, t2, t3);
                bl[2*nb][0] = t0; bl[2*nb][1] = t1;
                bl[2*nb+1][0] = t2; bl[2*nb+1][1] = t3;
            }
            #pragma unroll
            for (int mf = 0; mf < 4; mf++)
                #pragma unroll
                for (int nf = 0; nf < 4; nf++) {
                    mma_bf16(acc[mf][nf], ah[mf], bh[nf][0], bh[nf][1]);
                    mma_bf16(acc[mf][nf], ah[mf], bl[nf][0], bl[nf][1]);
                    mma_bf16(acc[mf][nf], al[mf], bh[nf][0], bh[nf][1]);
                }
        }
    }
}

// ---------------------------------------------------------------------------
// QKV GEMM: x @ W_attn + b -> split bf16 q/k/v at [b*h][t][d] (q *= 0.125)
// grid (18, 64)
// ---------------------------------------------------------------------------
__global__ __launch_bounds__(256) void qkv_mma(const float* __restrict__ bias) {
    extern __shared__ char sm[];
    const int bm = blockIdx.y * 128;
    const int bn = blockIdx.x * 128;
    float acc[4][4][4] = {};
    gemm_main(g_xhi, g_xlo, g_WaThi, g_WaTlo, bm, bn, acc, sm);

    const int wid = threadIdx.x >> 5, lane = threadIdx.x & 31;
    const int which = bn / CDIM;              // 0=q 1=k 2=v (tiles never straddle)
    const int batch = bm >> 12;
    const float sc = (which == 0) ? 0.125f : 1.0f;
    __nv_bfloat16* dhi = which == 0 ? g_qhi : which == 1 ? g_khi : g_vhi;
    __nv_bfloat16* dlo = which == 0 ? g_qlo : which == 1 ? g_klo : g_vlo;

    #pragma unroll
    for (int nf = 0; nf < 4; nf++) {
        const int gcol = bn + (wid >> 1) * 32 + nf * 8 + (lane & 3) * 2;
        const float b0 = __ldg(bias + gcol), b1 = __ldg(bias + gcol + 1);
        const int within = gcol % CDIM;
        const int head = within >> 6, d = within & 63;
        #pragma unroll
        for (int mf = 0; mf < 4; mf++) {
            const int t = (bm & (TDIM - 1)) + (wid & 1) * 64 + mf * 16 + (lane >> 2);
            size_t o0 = ((size_t)(batch*HDIM + head)*TDIM + t)     * DDIM + d;
            size_t o1 = ((size_t)(batch*HDIM + head)*TDIM + t + 8) * DDIM + d;
            split_store((acc[mf][nf][0]+b0)*sc, (acc[mf][nf][1]+b1)*sc, dhi, dlo, o0);
            split_store((acc[mf][nf][2]+b0)*sc, (acc[mf][nf][3]+b1)*sc, dhi, dlo, o1);
        }
    }
}

// ---------------------------------------------------------------------------
// Projection GEMM: y @ W_proj + b -> d_out fp32.  grid (6, 64)
// ---------------------------------------------------------------------------
__global__ __launch_bounds__(256) void proj_mma(const float* __restrict__ bias,
                                                float* __restrict__ out) {
    extern __shared__ char sm[];
    const int bm = blockIdx.y * 128;
    const int bn = blockIdx.x * 128;
    float acc[4][4][4] = {};
    gemm_main(g_yhi, g_ylo, g_WpThi, g_WpTlo, bm, bn, acc, sm);

    const int wid = threadIdx.x >> 5, lane = threadIdx.x & 31;
    #pragma unroll
    for (int nf = 0; nf < 4; nf++) {
        const int gcol = bn + (wid >> 1) * 32 + nf * 8 + (lane & 3) * 2;
        const float b0 = __ldg(bias + gcol), b1 = __ldg(bias + gcol + 1);
        #pragma unroll
        for (int mf = 0; mf < 4; mf++) {
            const int m = bm + (wid & 1) * 64 + mf * 16 + (lane >> 2);
            *(float2*)(out + (size_t)m * CDIM + gcol) =
                make_float2(acc[mf][nf][0] + b0, acc[mf][nf][1] + b1);
            *(float2*)(out + (size_t)(m + 8) * CDIM + gcol) =
                make_float2(acc[mf][nf][2] + b0, acc[mf][nf][3] + b1);
        }
    }
}

// ---------------------------------------------------------------------------
// Flash attention, split-bf16 HMMA.  grid (32 q-tiles, 24 bh), 256 thr.
// Q-tile 128 rows (warp w owns rows 16w..16w+15), K/V tiles 64 rows,
// cp.async double-buffered.  P stays in registers (S accum frags == PV A frags).
// smem stage 32KB: Khi@0 Klo@8K Vhi@16K Vlo@24K, [t][d] rows 128B SW128.
// Epilogue writes split bf16 into g_yhi/g_ylo.
// ---------------------------------------------------------------------------
#define FSMEM (2*32768)

__global__ __launch_bounds__(256, 1) void flash_mma() {
    extern __shared__ char sm[];
    const uint32_t sb = smem_u32(sm);
    const int tid = threadIdx.x, wid = tid >> 5, lane = tid & 31;
    const int qt = (int)gridDim.x - 1 - (int)blockIdx.x;   // heavy tiles first
    const int bh = blockIdx.y;
    const int qbase = qt * 128;
    const int ntiles = (qbase + 128) / 64;                  // 2qt+2

    const __nv_bfloat16* qhi = g_qhi + (size_t)bh * TDIM * DDIM;
    const __nv_bfloat16* qlo = g_qlo + (size_t)bh * TDIM * DDIM;
    const __nv_bfloat16* khi = g_khi + (size_t)bh * TDIM * DDIM;
    const __nv_bfloat16* klo = g_klo + (size_t)bh * TDIM * DDIM;
    const __nv_bfloat16* vhi = g_vhi + (size_t)bh * TDIM * DDIM;
    const __nv_bfloat16* vlo = g_vlo + (size_t)bh * TDIM * DDIM;

    // Q fragments, register resident: [kf][a], a-order: (r,klo),(r+8,klo),(r,khi),(r+8,khi)
    uint32_t qh[4][4], ql[4][4];
    {
        const int row = qbase + wid * 16 + (lane >> 2);
        const int colb = (lane & 3) * 2;
        #pragma unroll
        for (int kf = 0; kf < 4; kf++)
            #pragma unroll
            for (int a = 0; a < 4; a++) {
                int rr = row + ((a & 1) ? 8 : 0);
                int cc = kf * 16 + colb + ((a & 2) ? 8 : 0);
                qh[kf][a] = *(const uint32_t*)(qhi + (size_t)rr * DDIM + cc);
                ql[kf][a] = *(const uint32_t*)(qlo + (size_t)rr * DDIM + cc);
            }
    }

    float m0 = -1e30f, m1 = -1e30f, l0 = 0.f, l1 = 0.f;
    float o[8][4] = {};
    const int qhi_row = qbase + wid * 16 + 15;
    const int r = lane & 7, g = lane >> 3;
    const float LOG2E = 1.4426950408889634f;

    // K/V tile loader (cp.async, 8 x 16B per thread)
    auto issue = [&](int jt) {
        const int kb = jt * 64;
        const uint32_t stg = sb + (uint32_t)((jt & 1) << 15);
        #pragma unroll
        for (int arr = 0; arr < 4; arr++) {
            const __nv_bfloat16* base = arr == 0 ? khi : arr == 1 ? klo
                                      : arr == 2 ? vhi : vlo;
            #pragma unroll
            for (int i = 0; i < 2; i++) {
                int s2 = tid + (i << 8);            // 0..511
                int row = s2 >> 3, c16 = s2 & 7;
                cp16(stg + (arr << 13) + SW128((uint32_t)(row*128 + (c16 << 4))),
                     base + (size_t)(kb + row) * DDIM + (c16 << 3));
            }
        }
        CP_COMMIT();
    };
    issue(0);

    for (int jt = 0; jt < ntiles; jt++) {
        CP_WAIT0();
        __syncthreads();
        if (jt + 1 < ntiles) issue(jt + 1);
        const int kb = jt * 64;
        if (kb <= qhi_row) {                        // causal per-warp skip
            const uint32_t st = sb + (uint32_t)((jt & 1) << 15);

            // ---- S = Q K^T (3 passes) ----
            float s[8][4] = {};
            #pragma unroll
            for (int kf = 0; kf < 4; kf++) {
                const int k0 = kf * 16;
                #pragma unroll
                for (int nb = 0; nb < 4; nb++) {
                    uint32_t off = SW128((uint32_t)(
                        (nb*16 + ((g & 2) ? 8 : 0) + r) * 128 +
                        (k0 + ((g & 1) ? 8 : 0)) * 2));
                    uint32_t h0, h1, h2, h3, e0, e1, e2, e3;
                    ldm_x4(st + off,        h0, h1, h2, h3);   // Khi
                    ldm_x4(st + 8192 + off, e0, e1, e2, e3);   // Klo
                    mma_bf16(s[2*nb],   qh[kf], h0, h1);
                    mma_bf16(s[2*nb],   qh[kf], e0, e1);
                    mma_bf16(s[2*nb],   ql[kf], h0, h1);
                    mma_bf16(s[2*nb+1], qh[kf], h2, h3);
                    mma_bf16(s[2*nb+1], qh[kf], e2, e3);
                    mma_bf16(s[2*nb+1], ql[kf], h2, h3);
                }
            }

            // ---- causal mask (diagonal tiles only) ----
            const int row0 = qbase + wid * 16 + (lane >> 2);
            if (kb + 63 > row0) {
                #pragma unroll
                for (int nf = 0; nf < 8; nf++) {
                    int col = kb + nf * 8 + (lane & 3) * 2;
                    if (col     > row0)     s[nf][0] = -1e30f;
                    if (col + 1 > row0)     s[nf][1] = -1e30f;
                    if (col     > row0 + 8) s[nf][2] = -1e30f;
                    if (col + 1 > row0 + 8) s[nf][3] = -1e30f;
                }
            }

            // ---- online softmax ----
            float rmax0 = -1e30f, rmax1 = -1e30f;
            #pragma unroll
            for (int nf = 0; nf < 8; nf++) {
                rmax0 = fmaxf(rmax0, fmaxf(s[nf][0], s[nf][1]));
                rmax1 = fmaxf(rmax1, fmaxf(s[nf][2], s[nf][3]));
            }
            rmax0 = fmaxf(rmax0, __shfl_xor_sync(0xffffffffu, rmax0, 1));
            rmax0 = fmaxf(rmax0, __shfl_xor_sync(0xffffffffu, rmax0, 2));
            rmax1 = fmaxf(rmax1, __shfl_xor_sync(0xffffffffu, rmax1, 1));
            rmax1 = fmaxf(rmax1, __shfl_xor_sync(0xffffffffu, rmax1, 2));
            const float mn0 = fmaxf(m0, rmax0), mn1 = fmaxf(m1, rmax1);
            const float a0 = ex2f((m0 - mn0) * LOG2E);
            const float a1 = ex2f((m1 - mn1) * LOG2E);
            m0 = mn0; m1 = mn1;
            const float ml0 = mn0 * LOG2E, ml1 = mn1 * LOG2E;
            float rs0 = 0.f, rs1 = 0.f;
            #pragma unroll
            for (int nf = 0; nf < 8; nf++) {
                s[nf][0] = ex2f(fmaf(s[nf][0], LOG2E, -ml0));
                s[nf][1] = ex2f(fmaf(s[nf][1], LOG2E, -ml0));
                s[nf][2] = ex2f(fmaf(s[nf][2], LOG2E, -ml1));
                s[nf][3] = ex2f(fmaf(s[nf][3], LOG2E, -ml1));
                rs0 += s[nf][0] + s[nf][1];
                rs1 += s[nf][2] + s[nf][3];
            }
            rs0 += __shfl_xor_sync(0xffffffffu, rs0, 1);
            rs0 += __shfl_xor_sync(0xffffffffu, rs0, 2);
            rs1 += __shfl_xor_sync(0xffffffffu, rs1, 1);
            rs1 += __shfl_xor_sync(0xffffffffu, rs1, 2);
            l0 = l0 * a0 + rs0;
            l1 = l1 * a1 + rs1;
            #pragma unroll
            for (int nf = 0; nf < 8; nf++) {
                o[nf][0] *= a0; o[nf][1] *= a0;
                o[nf][2] *= a1; o[nf][3] *= a1;
            }

            // ---- P -> bf16 hi/lo A-fragments (registers only) ----
            uint32_t ph[4][4], pl[4][4];
            #pragma unroll
            for (int j = 0; j < 4; j++) {
                #pragma unroll
                for (int half = 0; half < 2; half++) {
                    float v0 = s[2*j + half][0], v1 = s[2*j + half][1];
                    float w0 = s[2*j + half][2], w1 = s[2*j + half][3];
                    uint32_t hA = pk2(v0, v1);
                    uint32_t hB = pk2(w0, w1);
                    ph[j][2*half]     = hA;
                    ph[j][2*half + 1] = hB;
                    pl[j][2*half] = pk2(v0 - __uint_as_float(hA << 16),
                                        v1 - __uint_as_float(hA & 0xffff0000u));
                    pl[j][2*half + 1] = pk2(w0 - __uint_as_float(hB << 16),
                                            w1 - __uint_as_float(hB & 0xffff0000u));
                }
            }
            // reorder: a-frag = {k-lo row, k-lo row+8, k-hi row, k-hi row+8}
            // ph[j] currently {acc2j rows, acc2j rows+8, acc2j+1 rows, acc2j+1 rows+8}
            // which is exactly {(r,klo),(r+8,klo),(r,khi),(r+8,khi)}  ✓

            // ---- O += P V (3 passes), V^T via ldmatrix.trans ----
            #pragma unroll
            for (int j = 0; j < 4; j++) {
                #pragma unroll
                for (int nb = 0; nb < 4; nb++) {
                    uint32_t off = SW128((uint32_t)(
                        (j*16 + ((g & 1) ? 8 : 0) + r) * 128 +
                        (nb*16 + ((g & 2) ? 8 : 0)) * 2));
                    uint32_t h0, h1, h2, h3, e0, e1, e2, e3;
                    ldm_x4t(st + 16384 + off, h0, h1, h2, h3);  // Vhi
                    ldm_x4t(st + 24576 + off, e0, e1, e2, e3);  // Vlo
                    mma_bf16(o[2*nb],   ph[j], h0, h1);
                    mma_bf16(o[2*nb],   pl[j], h0, h1);
                    mma_bf16(o[2*nb],   ph[j], e0, e1);
                    mma_bf16(o[2*nb+1], ph[j], h2, h3);
                    mma_bf16(o[2*nb+1], pl[j], h2, h3);
                    mma_bf16(o[2*nb+1], ph[j], e2, e3);
                }
            }
        }
    }

    // ---- epilogue: o / l, split to bf16 hi/lo into g_y ----
    const float inv0 = 1.0f / l0, inv1 = 1.0f / l1;
    const int batch = bh / HDIM, hh = bh % HDIM;
    const int row = qbase + wid * 16 + (lane >> 2);
    const size_t rb0 = ((size_t)(batch * TDIM + row))     * CDIM + hh * DDIM;
    const size_t rb1 = ((size_t)(batch * TDIM + row + 8)) * CDIM + hh * DDIM;
    #pragma unroll
    for (int nf = 0; nf < 8; nf++) {
        const int d = nf * 8 + (lane & 3) * 2;
        split_store(o[nf][0] * inv0, o[nf][1] * inv0, g_yhi, g_ylo, rb0 + d);
        split_store(o[nf][2] * inv1, o[nf][3] * inv1, g_yhi, g_ylo, rb1 + d);
    }
}

// ---------------------------------------------------------------------------
extern "C" void kernel_launch(void* const* d_in, const int* in_sizes, int n_in,
                              void* d_out, int out_size) {
    const float *x = nullptr, *Wa = nullptr, *ba = nullptr, *Wp = nullptr, *bp = nullptr;
    for (int i = 0; i < n_in; i++) {
        switch (in_sizes[i]) {
            case 6291456: x  = (const float*)d_in[i]; break;   // [2,4096,768]
            case 1769472: Wa = (const float*)d_in[i]; break;   // [768,2304]
            case 2304:    ba = (const float*)d_in[i]; break;
            case 589824:  Wp = (const float*)d_in[i]; break;   // [768,768]
            case 768:     bp = (const float*)d_in[i]; break;
        }
    }

    cudaFuncSetAttribute(qkv_mma,   cudaFuncAttributeMaxDynamicSharedMemorySize, GSMEM);
    cudaFuncSetAttribute(proj_mma,  cudaFuncAttributeMaxDynamicSharedMemorySize, GSMEM);
    cudaFuncSetAttribute(flash_mma, cudaFuncAttributeMaxDynamicSharedMemorySize, FSMEM);

    __nv_bfloat16 *xhi, *xlo, *wahi, *walo, *wphi, *wplo;
    cudaGetSymbolAddress((void**)&xhi,  g_xhi);
    cudaGetSymbolAddress((void**)&xlo,  g_xlo);
    cudaGetSymbolAddress((void**)&wahi, g_WaThi);
    cudaGetSymbolAddress((void**)&walo, g_WaTlo);
    cudaGetSymbolAddress((void**)&wphi, g_WpThi);
    cudaGetSymbolAddress((void**)&wplo, g_WpTlo);

    split_bf16<<<(MTOT*CDIM/2 + 255)/256, 256>>>(x, xhi, xlo, MTOT*CDIM/2);
    wsplit_T<<<dim3(N3DIM/32, CDIM/32), dim3(32, 8)>>>(Wa, wahi, walo, CDIM, N3DIM);
    wsplit_T<<<dim3(CDIM/32,  CDIM/32), dim3(32, 8)>>>(Wp, wphi, wplo, CDIM, CDIM);
    qkv_mma<<<dim3(N3DIM/128, MTOT/128), 256, GSMEM>>>(ba);        // (18,64)
    flash_mma<<<dim3(TDIM/128, BDIM*HDIM), 256, FSMEM>>>();        // (32,24)
    proj_mma<<<dim3(CDIM/128, MTOT/128), 256, GSMEM>>>(bp, (float*)d_out); // (6,64)
}